// round 13
// baseline (speedup 1.0000x reference)
#include <cuda_runtime.h>
#include <math.h>

// Problem dims (fixed per reference)
#define B_DIM   8192
#define N_DIM   512
#define K_SPL   8
#define H_DIM   1024
#define OUT_DIM (N_DIM * (2 * K_SPL + 1))   // 8704

// Scratch: __device__ globals (allocation-free rule)
__device__ float g_x1[(size_t)B_DIM * H_DIM];           // 33.5 MB
__device__ float g_x2[(size_t)B_DIM * H_DIM];           // 33.5 MB
__device__ float g_net[(size_t)B_DIM * OUT_DIM];        // 285 MB

// ---------------------------------------------------------------------------
// GEMM: C[M,Nn] = tanh( f(A)[M,Kk] @ Bm[Kk,Nn] + bias[Nn] ),  f = (x-0.5) opt.
// 128x128 block tile, BK=16, 256 threads, 8x8 per thread. All dims assumed
// multiples of the tile (true for this problem: M=8192, Nn in {1024,8704},
// Kk in {512,1024}).
// ---------------------------------------------------------------------------
template <bool SUBHALF>
__global__ void __launch_bounds__(256)
gemm_bias_tanh(const float* __restrict__ A,  int lda,
               const float* __restrict__ Bm, int ldb,
               const float* __restrict__ bias,
               float* __restrict__ C, int ldc,
               int Kk)
{
    constexpr int BM = 128, BN = 128, BK = 16;
    __shared__ float As[BK][BM];
    __shared__ float Bs[BK][BN];

    const int tid  = threadIdx.x;
    const int row0 = blockIdx.y * BM;
    const int col0 = blockIdx.x * BN;

    // A tile loader: 128 rows x 16 cols; each thread: 8 floats (two float4)
    const int a_row = tid >> 1;           // 0..127
    const int a_col = (tid & 1) * 8;      // 0 or 8
    // B tile loader: 16 rows x 128 cols; each thread: 8 floats (two float4)
    const int b_row = tid >> 4;           // 0..15
    const int b_col = (tid & 15) * 8;     // 0..120

    const int tx = tid & 15;              // column group
    const int ty = tid >> 4;              // row group

    float acc[8][8];
#pragma unroll
    for (int i = 0; i < 8; i++)
#pragma unroll
        for (int j = 0; j < 8; j++) acc[i][j] = 0.0f;

    const float* Ap = A  + (size_t)(row0 + a_row) * lda + a_col;
    const float* Bp = Bm + (size_t)b_row * ldb + col0 + b_col;

    for (int k0 = 0; k0 < Kk; k0 += BK) {
        float4 a0 = *(const float4*)(Ap);
        float4 a1 = *(const float4*)(Ap + 4);
        if (SUBHALF) {
            a0.x -= 0.5f; a0.y -= 0.5f; a0.z -= 0.5f; a0.w -= 0.5f;
            a1.x -= 0.5f; a1.y -= 0.5f; a1.z -= 0.5f; a1.w -= 0.5f;
        }
        As[a_col + 0][a_row] = a0.x;
        As[a_col + 1][a_row] = a0.y;
        As[a_col + 2][a_row] = a0.z;
        As[a_col + 3][a_row] = a0.w;
        As[a_col + 4][a_row] = a1.x;
        As[a_col + 5][a_row] = a1.y;
        As[a_col + 6][a_row] = a1.z;
        As[a_col + 7][a_row] = a1.w;

        float4 bv0 = *(const float4*)(Bp);
        float4 bv1 = *(const float4*)(Bp + 4);
        *(float4*)&Bs[b_row][b_col]     = bv0;
        *(float4*)&Bs[b_row][b_col + 4] = bv1;

        __syncthreads();

#pragma unroll
        for (int kk = 0; kk < BK; kk++) {
            float af[8], bf[8];
            *(float4*)(af)     = *(const float4*)&As[kk][ty * 8];
            *(float4*)(af + 4) = *(const float4*)&As[kk][ty * 8 + 4];
            *(float4*)(bf)     = *(const float4*)&Bs[kk][tx * 8];
            *(float4*)(bf + 4) = *(const float4*)&Bs[kk][tx * 8 + 4];
#pragma unroll
            for (int i = 0; i < 8; i++)
#pragma unroll
                for (int j = 0; j < 8; j++)
                    acc[i][j] = fmaf(af[i], bf[j], acc[i][j]);
        }
        __syncthreads();

        Ap += BK;
        Bp += (size_t)BK * ldb;
    }

    // Epilogue: bias + tanh, vectorized store
    float bb[8];
#pragma unroll
    for (int j = 0; j < 8; j++) bb[j] = bias[col0 + tx * 8 + j];

#pragma unroll
    for (int i = 0; i < 8; i++) {
        float r[8];
#pragma unroll
        for (int j = 0; j < 8; j++) r[j] = tanhf(acc[i][j] + bb[j]);
        float* Cp = C + (size_t)(row0 + ty * 8 + i) * ldc + col0 + tx * 8;
        *(float4*)(Cp)     = *(const float4*)(r);
        *(float4*)(Cp + 4) = *(const float4*)(r + 4);
    }
}

// ---------------------------------------------------------------------------
// Spline transform + log-density reduction.
// One block per batch row b (8192 blocks), one thread per spline dim n (512).
// Reads net[b, n, 0:17]  (first 9 = h_net, last 8 = w_net).
// Output layout: [ v_out (B x 2N) | log_density_out (B) ], fp32.
// ---------------------------------------------------------------------------
__global__ void __launch_bounds__(512)
spline_kernel(const float* __restrict__ v_in,
              const float* __restrict__ logd,
              const float* __restrict__ net,
              float* __restrict__ out)
{
    __shared__ float red[16];
    const int b = blockIdx.x;
    const int n = threadIdx.x;

    const float* p = net + (size_t)b * OUT_DIM + (size_t)n * (2 * K_SPL + 1);

    float h[K_SPL + 1];
#pragma unroll
    for (int i = 0; i <= K_SPL; i++) h[i] = p[i];
    float w[K_SPL];
#pragma unroll
    for (int j = 0; j < K_SPL; j++) w[j] = p[K_SPL + 1 + j];

    // softmax over w (K=8)
    float m = w[0];
#pragma unroll
    for (int j = 1; j < K_SPL; j++) m = fmaxf(m, w[j]);
    float s = 0.0f;
#pragma unroll
    for (int j = 0; j < K_SPL; j++) { w[j] = expf(w[j] - m); s += w[j]; }
    const float inv_s = 1.0f / s;
#pragma unroll
    for (int j = 0; j < K_SPL; j++) w[j] *= inv_s;

    // h_norm
    float eh[K_SPL + 1];
#pragma unroll
    for (int i = 0; i <= K_SPL; i++) eh[i] = expf(h[i]);
    float denom = 0.0f;
#pragma unroll
    for (int j = 0; j < K_SPL; j++) denom += 0.5f * w[j] * (eh[j] + eh[j + 1]);
    const float inv_d = 1.0f / denom;
    float hn[K_SPL + 1];
#pragma unroll
    for (int i = 0; i <= K_SPL; i++) hn[i] = eh[i] * inv_d;

    const float vp = v_in[(size_t)b * (2 * N_DIM) + n];
    const float va = v_in[(size_t)b * (2 * N_DIM) + N_DIM + n];

    // segment index: k = clip(count(knots_x < va) - 1, 0, K-1)
    int cnt = (0.0f < va) ? 1 : 0;
    {
        float cum = 0.0f;
#pragma unroll
        for (int j = 0; j < K_SPL; j++) {
            cum += w[j];
            cnt += (cum < va) ? 1 : 0;
        }
    }
    int k = cnt - 1;
    k = k < 0 ? 0 : (k > K_SPL - 1 ? K_SPL - 1 : k);

    // select segment quantities (unrolled predicated select, keeps regs)
    float xlo = 0.0f, ylo = 0.0f;
    float wseg = w[0], hlo = hn[0], hhi = hn[1];
    {
        float cum = 0.0f, ysum = 0.0f;
#pragma unroll
        for (int j = 0; j < K_SPL; j++) {
            if (j == k) { xlo = cum; ylo = ysum; wseg = w[j]; hlo = hn[j]; hhi = hn[j + 1]; }
            cum  += w[j];
            ysum += 0.5f * w[j] * (hn[j] + hn[j + 1]);
        }
    }

    const float alpha = (va - xlo) / wseg;
    const float vo = ylo + alpha * hlo * wseg
                   + 0.5f * alpha * alpha * (hhi - hlo) * wseg;

    out[(size_t)b * (2 * N_DIM) + n]        = vp;
    out[(size_t)b * (2 * N_DIM) + N_DIM + n] = vo;

    // log-density contribution, block reduction over 512 threads
    float lg = logf(hlo + alpha * (hhi - hlo));
#pragma unroll
    for (int off = 16; off > 0; off >>= 1)
        lg += __shfl_down_sync(0xffffffffu, lg, off);
    if ((n & 31) == 0) red[n >> 5] = lg;
    __syncthreads();
    if (n < 16) {
        float v = red[n];
#pragma unroll
        for (int off = 8; off > 0; off >>= 1)
            v += __shfl_down_sync(0x0000ffffu, v, off);
        if (n == 0)
            out[(size_t)B_DIM * (2 * N_DIM) + b] = logd[b] - v;
    }
}

// ---------------------------------------------------------------------------
// Launch
// ---------------------------------------------------------------------------
extern "C" void kernel_launch(void* const* d_in, const int* in_sizes, int n_in,
                              void* d_out, int out_size)
{
    const float* v_in = (const float*)d_in[0];   // [B, 2N]
    const float* logd = (const float*)d_in[1];   // [B, 1]
    const float* W1   = (const float*)d_in[2];   // [N, H]
    const float* b1   = (const float*)d_in[3];   // [H]
    const float* W2   = (const float*)d_in[4];   // [H, H]
    const float* b2   = (const float*)d_in[5];   // [H]
    const float* W3   = (const float*)d_in[6];   // [H, OUT_DIM]
    const float* b3   = (const float*)d_in[7];   // [OUT_DIM]
    float* out = (float*)d_out;

    float *x1, *x2, *net;
    cudaGetSymbolAddress((void**)&x1,  g_x1);
    cudaGetSymbolAddress((void**)&x2,  g_x2);
    cudaGetSymbolAddress((void**)&net, g_net);

    dim3 blk(256);

    // G1: x1 = tanh((v_passive - 0.5) @ W1 + b1)   [8192,512]x[512,1024]
    {
        dim3 grid(H_DIM / 128, B_DIM / 128);
        gemm_bias_tanh<true><<<grid, blk>>>(v_in, 2 * N_DIM, W1, H_DIM, b1,
                                            x1, H_DIM, N_DIM);
    }
    // G2: x2 = tanh(x1 @ W2 + b2)                  [8192,1024]x[1024,1024]
    {
        dim3 grid(H_DIM / 128, B_DIM / 128);
        gemm_bias_tanh<false><<<grid, blk>>>(x1, H_DIM, W2, H_DIM, b2,
                                             x2, H_DIM, H_DIM);
    }
    // G3: net = tanh(x2 @ W3 + b3)                 [8192,1024]x[1024,8704]
    {
        dim3 grid(OUT_DIM / 128, B_DIM / 128);
        gemm_bias_tanh<false><<<grid, blk>>>(x2, H_DIM, W3, OUT_DIM, b3,
                                             net, OUT_DIM, H_DIM);
    }
    // Spline + log-density
    spline_kernel<<<B_DIM, 512>>>(v_in, logd, net, out);
}

// round 15
// speedup vs baseline: 1.5626x; 1.5626x over previous
#include <cuda_runtime.h>
#include <cuda_bf16.h>
#include <math.h>
#include <stdint.h>

// ---------------------------------------------------------------------------
// Problem dims (fixed)
// ---------------------------------------------------------------------------
#define B_DIM   8192
#define N_DIM   512
#define K_SPL   8
#define H_DIM   1024
#define OUT_DIM (N_DIM * (2 * K_SPL + 1))   // 8704
#define KP1     (3 * N_DIM)                 // 1536
#define KP2     (3 * H_DIM)                 // 3072

// ---------------------------------------------------------------------------
// Scratch (__device__ globals).
// A' = [Ah | Ah | Al],  B' = [Bh | Bl | Bh] along K  =>
//   A'@B'^T = Ah·Bh + Ah·Bl + Al·Bh  (drops Al·Bl ~ 2^-16)
// ---------------------------------------------------------------------------
__device__ __align__(128) __nv_bfloat16 g_A1[(size_t)B_DIM * KP1];
__device__ __align__(128) __nv_bfloat16 g_A2[(size_t)B_DIM * KP2];
__device__ __align__(128) __nv_bfloat16 g_A3[(size_t)B_DIM * KP2];
__device__ __align__(128) __nv_bfloat16 g_B1[(size_t)H_DIM * KP1];
__device__ __align__(128) __nv_bfloat16 g_B2[(size_t)H_DIM * KP2];
__device__ __align__(128) __nv_bfloat16 g_B3[(size_t)OUT_DIM * KP2];
__device__ __align__(128) float         g_net[(size_t)B_DIM * OUT_DIM];

// ---------------------------------------------------------------------------
// Helpers (all baseline sm_80+ PTX — compiles under compute_103)
// ---------------------------------------------------------------------------
__device__ __forceinline__ uint32_t smem_u32(const void* p) {
    uint32_t a;
    asm("{ .reg .u64 t; cvta.to.shared.u64 t, %1; cvt.u32.u64 %0, t; }"
        : "=r"(a) : "l"(p));
    return a;
}

#define CP_ASYNC16(dst, src) \
    asm volatile("cp.async.cg.shared.global [%0], [%1], 16;" \
                 :: "r"(dst), "l"(src) : "memory")
#define CP_COMMIT() asm volatile("cp.async.commit_group;" ::: "memory")
#define CP_WAIT2()  asm volatile("cp.async.wait_group 2;" ::: "memory")

#define LDSM_X4(r0, r1, r2, r3, addr) \
    asm volatile("ldmatrix.sync.aligned.m8n8.x4.shared.b16 {%0,%1,%2,%3}, [%4];" \
                 : "=r"(r0), "=r"(r1), "=r"(r2), "=r"(r3) : "r"(addr))

#define MMA_BF16(d, a0, a1, a2, a3, b0, b1) \
    asm volatile("mma.sync.aligned.m16n8k16.row.col.f32.bf16.bf16.f32 " \
                 "{%0,%1,%2,%3}, {%4,%5,%6,%7}, {%8,%9}, {%0,%1,%2,%3};" \
                 : "+f"((d)[0]), "+f"((d)[1]), "+f"((d)[2]), "+f"((d)[3]) \
                 : "r"(a0), "r"(a1), "r"(a2), "r"(a3), "r"(b0), "r"(b1))

__device__ __forceinline__ void bsplit(float a, __nv_bfloat16& hi, __nv_bfloat16& lo) {
    hi = __float2bfloat16(a);
    lo = __float2bfloat16(a - __bfloat162float(hi));
}

// ---------------------------------------------------------------------------
// HMMA GEMM: C[128x128 tile] = tanh( A'[M,KP] @ B'[N,KP]^T + bias )
// 256 threads = 8 warps (2 M x 4 N), warp tile 64x32, BK=32, 4-stage cp.async.
// SMEM row = 32 bf16 (64 B) padded to 80 B -> conflict-free ldmatrix.
//   MODE 0: fp32 out to Cf (ldc = OUT_DIM)
//   MODE 1: bf16 triple [hi|hi|lo] to Cb (row stride KP2, segment H_DIM)
// ---------------------------------------------------------------------------
#define BK        32
#define ROWB      80                       // padded row stride (bytes)
#define TILE_B    (128 * ROWB)             // 10240 per operand per stage
#define STAGES    4
#define SMEM_SZ   (2 * STAGES * TILE_B)    // 81920

template <int MODE>
__global__ void __launch_bounds__(256, 1)
hmma_gemm(const __nv_bfloat16* __restrict__ A,
          const __nv_bfloat16* __restrict__ Bw,
          const float* __restrict__ bias,
          float* __restrict__ Cf,
          __nv_bfloat16* __restrict__ Cb,
          int KP)
{
    extern __shared__ char smem[];
    const uint32_t sb = smem_u32(smem);
    const int tid  = threadIdx.x;
    const int wid  = tid >> 5;
    const int lane = tid & 31;
    const int warp_m = wid & 1;            // 0..1  (64 rows each)
    const int warp_n = wid >> 1;           // 0..3  (32 cols each)
    const int row0 = blockIdx.y * 128;
    const int col0 = blockIdx.x * 128;

    const __nv_bfloat16* Ag = A  + (size_t)row0 * KP;
    const __nv_bfloat16* Bg = Bw + (size_t)col0 * KP;
    const int nc = KP / BK;

    // per-thread loader coords: 512 16B-chunks per operand per stage
    const int l_row0 = tid >> 2;           // chunk idx = tid, tid+256
    const int l_chk0 = (tid & 3) * 16;     // byte offset within 64B row
    const int l_row1 = (tid + 256) >> 2;
    const int l_chk1 = ((tid + 256) & 3) * 16;

    auto load_stage = [&](int buf, int c) {
        const int k0 = c * BK;
        uint32_t a_s = sb + buf * TILE_B;
        uint32_t b_s = sb + STAGES * TILE_B + buf * TILE_B;
        const char* ap = (const char*)(Ag + k0);
        const char* bp = (const char*)(Bg + k0);
        CP_ASYNC16(a_s + l_row0 * ROWB + l_chk0, ap + (size_t)l_row0 * KP * 2 + l_chk0);
        CP_ASYNC16(a_s + l_row1 * ROWB + l_chk1, ap + (size_t)l_row1 * KP * 2 + l_chk1);
        CP_ASYNC16(b_s + l_row0 * ROWB + l_chk0, bp + (size_t)l_row0 * KP * 2 + l_chk0);
        CP_ASYNC16(b_s + l_row1 * ROWB + l_chk1, bp + (size_t)l_row1 * KP * 2 + l_chk1);
    };

    float acc[4][4][4];
#pragma unroll
    for (int i = 0; i < 4; i++)
#pragma unroll
        for (int j = 0; j < 4; j++)
#pragma unroll
            for (int e = 0; e < 4; e++) acc[i][j][e] = 0.0f;

    // prologue: stages 0..2
#pragma unroll
    for (int s = 0; s < STAGES - 1; ++s) {
        if (s < nc) load_stage(s, s);
        CP_COMMIT();
    }

    // ldmatrix per-lane address components (within a stage buffer)
    const uint32_t a_lm_off =
        (uint32_t)((warp_m * 64 + (lane & 15)) * ROWB + (lane >> 4) * 16);
    const uint32_t b_lm_off =
        (uint32_t)((warp_n * 32 + (lane & 7) + ((lane >> 4) << 3)) * ROWB
                   + ((lane >> 3) & 1) * 16);

    for (int c = 0; c < nc; ++c) {
        CP_WAIT2();
        __syncthreads();
        if (c + STAGES - 1 < nc) load_stage((c + STAGES - 1) & (STAGES - 1), c + STAGES - 1);
        CP_COMMIT();

        const int buf = c & (STAGES - 1);
        const uint32_t a_s = sb + buf * TILE_B;
        const uint32_t b_s = sb + STAGES * TILE_B + buf * TILE_B;

#pragma unroll
        for (int kk = 0; kk < 2; ++kk) {               // two k16 steps
            const uint32_t koff = (uint32_t)(kk * 32); // 16 bf16 = 32 B
            uint32_t a[4][4], b[4][2];
#pragma unroll
            for (int mt = 0; mt < 4; ++mt) {
                uint32_t addr = a_s + a_lm_off + (uint32_t)(mt * 16 * ROWB) + koff;
                LDSM_X4(a[mt][0], a[mt][1], a[mt][2], a[mt][3], addr);
            }
#pragma unroll
            for (int np = 0; np < 2; ++np) {
                uint32_t addr = b_s + b_lm_off + (uint32_t)(np * 16 * ROWB) + koff;
                LDSM_X4(b[np * 2][0], b[np * 2][1], b[np * 2 + 1][0], b[np * 2 + 1][1], addr);
            }
#pragma unroll
            for (int mt = 0; mt < 4; ++mt)
#pragma unroll
                for (int nt = 0; nt < 4; ++nt)
                    MMA_BF16(acc[mt][nt], a[mt][0], a[mt][1], a[mt][2], a[mt][3],
                             b[nt][0], b[nt][1]);
        }
    }

    // epilogue: thread t holds (r_lo, c),(r_lo, c+1),(r_hi, c),(r_hi, c+1)
#pragma unroll
    for (int mt = 0; mt < 4; ++mt) {
        const int r_lo = row0 + warp_m * 64 + mt * 16 + (lane >> 2);
#pragma unroll
        for (int nt = 0; nt < 4; ++nt) {
            const int gc = col0 + warp_n * 32 + nt * 8 + (lane & 3) * 2;
            const float b0 = bias[gc], b1 = bias[gc + 1];
#pragma unroll
            for (int h = 0; h < 2; ++h) {
                const int r = r_lo + h * 8;
                float t0 = tanhf(acc[mt][nt][h * 2 + 0] + b0);
                float t1 = tanhf(acc[mt][nt][h * 2 + 1] + b1);
                if (MODE == 0) {
                    float2 v = make_float2(t0, t1);
                    *(float2*)(Cf + (size_t)r * OUT_DIM + gc) = v;
                } else {
                    __nv_bfloat16 h0, l0, h1, l1;
                    bsplit(t0, h0, l0);
                    bsplit(t1, h1, l1);
                    __nv_bfloat162 hh = __halves2bfloat162(h0, h1);
                    __nv_bfloat162 ll = __halves2bfloat162(l0, l1);
                    __nv_bfloat16* outp = Cb + (size_t)r * KP2;
                    *(__nv_bfloat162*)(outp + gc)              = hh;
                    *(__nv_bfloat162*)(outp + H_DIM + gc)      = hh;
                    *(__nv_bfloat162*)(outp + 2 * H_DIM + gc)  = ll;
                }
            }
        }
    }
}

// ---------------------------------------------------------------------------
// Prep kernels
// ---------------------------------------------------------------------------
__global__ void prep_v(const float* __restrict__ v_in, __nv_bfloat16* __restrict__ A1)
{
    int i = blockIdx.x * blockDim.x + threadIdx.x;
    if (i >= B_DIM * N_DIM) return;
    int m = i / N_DIM, k = i % N_DIM;
    float a = v_in[(size_t)m * (2 * N_DIM) + k] - 0.5f;
    __nv_bfloat16 hi, lo;
    bsplit(a, hi, lo);
    size_t base = (size_t)m * KP1;
    A1[base + k]             = hi;
    A1[base + N_DIM + k]     = hi;
    A1[base + 2 * N_DIM + k] = lo;
}

// W[Kk, Nn] row-major -> B'[Nn, 3*Kk]: [hi | lo | hi]
__global__ void prep_w(const float* __restrict__ W, __nv_bfloat16* __restrict__ Bp,
                       int Kk, int Nn)
{
    int idx = blockIdx.x * blockDim.x + threadIdx.x;
    if (idx >= Kk * Nn) return;
    int k = idx / Nn, n = idx % Nn;
    __nv_bfloat16 hi, lo;
    bsplit(W[idx], hi, lo);
    size_t base = (size_t)n * (3 * Kk);
    Bp[base + k]          = hi;
    Bp[base + Kk + k]     = lo;
    Bp[base + 2 * Kk + k] = hi;
}

// ---------------------------------------------------------------------------
// Spline transform + log-density (unchanged; ~memory-bound at 97us)
// ---------------------------------------------------------------------------
__global__ void __launch_bounds__(512)
spline_kernel(const float* __restrict__ v_in,
              const float* __restrict__ logd,
              const float* __restrict__ net,
              float* __restrict__ out)
{
    __shared__ float red[16];
    const int b = blockIdx.x;
    const int n = threadIdx.x;

    const float* p = net + (size_t)b * OUT_DIM + (size_t)n * (2 * K_SPL + 1);

    float h[K_SPL + 1];
#pragma unroll
    for (int i = 0; i <= K_SPL; i++) h[i] = p[i];
    float w[K_SPL];
#pragma unroll
    for (int j = 0; j < K_SPL; j++) w[j] = p[K_SPL + 1 + j];

    float m = w[0];
#pragma unroll
    for (int j = 1; j < K_SPL; j++) m = fmaxf(m, w[j]);
    float s = 0.0f;
#pragma unroll
    for (int j = 0; j < K_SPL; j++) { w[j] = expf(w[j] - m); s += w[j]; }
    const float inv_s = 1.0f / s;
#pragma unroll
    for (int j = 0; j < K_SPL; j++) w[j] *= inv_s;

    float eh[K_SPL + 1];
#pragma unroll
    for (int i = 0; i <= K_SPL; i++) eh[i] = expf(h[i]);
    float denom = 0.0f;
#pragma unroll
    for (int j = 0; j < K_SPL; j++) denom += 0.5f * w[j] * (eh[j] + eh[j + 1]);
    const float inv_d = 1.0f / denom;
    float hn[K_SPL + 1];
#pragma unroll
    for (int i = 0; i <= K_SPL; i++) hn[i] = eh[i] * inv_d;

    const float vp = v_in[(size_t)b * (2 * N_DIM) + n];
    const float va = v_in[(size_t)b * (2 * N_DIM) + N_DIM + n];

    int cnt = (0.0f < va) ? 1 : 0;
    {
        float cum = 0.0f;
#pragma unroll
        for (int j = 0; j < K_SPL; j++) {
            cum += w[j];
            cnt += (cum < va) ? 1 : 0;
        }
    }
    int k = cnt - 1;
    k = k < 0 ? 0 : (k > K_SPL - 1 ? K_SPL - 1 : k);

    float xlo = 0.0f, ylo = 0.0f;
    float wseg = w[0], hlo = hn[0], hhi = hn[1];
    {
        float cum = 0.0f, ysum = 0.0f;
#pragma unroll
        for (int j = 0; j < K_SPL; j++) {
            if (j == k) { xlo = cum; ylo = ysum; wseg = w[j]; hlo = hn[j]; hhi = hn[j + 1]; }
            cum  += w[j];
            ysum += 0.5f * w[j] * (hn[j] + hn[j + 1]);
        }
    }

    const float alpha = (va - xlo) / wseg;
    const float vo = ylo + alpha * hlo * wseg
                   + 0.5f * alpha * alpha * (hhi - hlo) * wseg;

    out[(size_t)b * (2 * N_DIM) + n]         = vp;
    out[(size_t)b * (2 * N_DIM) + N_DIM + n] = vo;

    float lg = logf(hlo + alpha * (hhi - hlo));
#pragma unroll
    for (int off = 16; off > 0; off >>= 1)
        lg += __shfl_down_sync(0xffffffffu, lg, off);
    if ((n & 31) == 0) red[n >> 5] = lg;
    __syncthreads();
    if (n < 16) {
        float v = red[n];
#pragma unroll
        for (int off = 8; off > 0; off >>= 1)
            v += __shfl_down_sync(0x0000ffffu, v, off);
        if (n == 0)
            out[(size_t)B_DIM * (2 * N_DIM) + b] = logd[b] - v;
    }
}

// ---------------------------------------------------------------------------
// Launch
// ---------------------------------------------------------------------------
extern "C" void kernel_launch(void* const* d_in, const int* in_sizes, int n_in,
                              void* d_out, int out_size)
{
    const float* v_in = (const float*)d_in[0];
    const float* logd = (const float*)d_in[1];
    const float* W1   = (const float*)d_in[2];
    const float* b1   = (const float*)d_in[3];
    const float* W2   = (const float*)d_in[4];
    const float* b2   = (const float*)d_in[5];
    const float* W3   = (const float*)d_in[6];
    const float* b3   = (const float*)d_in[7];
    float* out = (float*)d_out;

    __nv_bfloat16 *A1, *A2, *A3, *B1v, *B2v, *B3v;
    float* net;
    cudaGetSymbolAddress((void**)&A1, g_A1);
    cudaGetSymbolAddress((void**)&A2, g_A2);
    cudaGetSymbolAddress((void**)&A3, g_A3);
    cudaGetSymbolAddress((void**)&B1v, g_B1);
    cudaGetSymbolAddress((void**)&B2v, g_B2);
    cudaGetSymbolAddress((void**)&B3v, g_B3);
    cudaGetSymbolAddress((void**)&net, g_net);

    cudaFuncSetAttribute((const void*)hmma_gemm<0>,
                         cudaFuncAttributeMaxDynamicSharedMemorySize, SMEM_SZ);
    cudaFuncSetAttribute((const void*)hmma_gemm<1>,
                         cudaFuncAttributeMaxDynamicSharedMemorySize, SMEM_SZ);

    // operand splitting / weight transpose
    prep_v<<<(B_DIM * N_DIM + 255) / 256, 256>>>(v_in, A1);
    prep_w<<<(N_DIM * H_DIM + 255) / 256, 256>>>(W1, B1v, N_DIM, H_DIM);
    prep_w<<<(H_DIM * H_DIM + 255) / 256, 256>>>(W2, B2v, H_DIM, H_DIM);
    prep_w<<<(H_DIM * OUT_DIM + 255) / 256, 256>>>(W3, B3v, H_DIM, OUT_DIM);

    // G1: x1 (bf16 triple) = tanh((v_p - 0.5) @ W1 + b1)
    hmma_gemm<1><<<dim3(H_DIM / 128, B_DIM / 128), 256, SMEM_SZ>>>(
        A1, B1v, b1, nullptr, A2, KP1);
    // G2: x2 (bf16 triple) = tanh(x1 @ W2 + b2)
    hmma_gemm<1><<<dim3(H_DIM / 128, B_DIM / 128), 256, SMEM_SZ>>>(
        A2, B2v, b2, nullptr, A3, KP2);
    // G3: net (fp32) = tanh(x2 @ W3 + b3)
    hmma_gemm<0><<<dim3(OUT_DIM / 128, B_DIM / 128), 256, SMEM_SZ>>>(
        A3, B3v, b3, net, nullptr, KP2);

    // spline + log-density
    spline_kernel<<<B_DIM, 512>>>(v_in, logd, net, out);
}

// round 16
// speedup vs baseline: 1.5642x; 1.0010x over previous
#include <cuda_runtime.h>
#include <cuda_bf16.h>
#include <math.h>
#include <stdint.h>

// ---------------------------------------------------------------------------
// Problem dims (fixed)
// ---------------------------------------------------------------------------
#define B_DIM   8192
#define N_DIM   512
#define K_SPL   8
#define H_DIM   1024
#define OUT_DIM (N_DIM * (2 * K_SPL + 1))   // 8704
#define KP1     (3 * N_DIM)                 // 1536
#define KP2     (3 * H_DIM)                 // 3072

// ---------------------------------------------------------------------------
// Scratch (__device__ globals).
// A' = [Ah | Ah | Al],  B' = [Bh | Bl | Bh] along K  =>
//   A'@B'^T = Ah·Bh + Ah·Bl + Al·Bh  (drops Al·Bl ~ 2^-16)
// ---------------------------------------------------------------------------
__device__ __align__(128) __nv_bfloat16 g_A1[(size_t)B_DIM * KP1];
__device__ __align__(128) __nv_bfloat16 g_A2[(size_t)B_DIM * KP2];
__device__ __align__(128) __nv_bfloat16 g_A3[(size_t)B_DIM * KP2];
__device__ __align__(128) __nv_bfloat16 g_B1[(size_t)H_DIM * KP1];
__device__ __align__(128) __nv_bfloat16 g_B2[(size_t)H_DIM * KP2];
__device__ __align__(128) __nv_bfloat16 g_B3[(size_t)OUT_DIM * KP2];
__device__ __align__(128) float         g_net[(size_t)B_DIM * OUT_DIM];

// ---------------------------------------------------------------------------
// Helpers (all baseline sm_80+ PTX — compiles under compute_103)
// ---------------------------------------------------------------------------
__device__ __forceinline__ uint32_t smem_u32(const void* p) {
    uint32_t a;
    asm("{ .reg .u64 t; cvta.to.shared.u64 t, %1; cvt.u32.u64 %0, t; }"
        : "=r"(a) : "l"(p));
    return a;
}

#define CP_ASYNC16(dst, src) \
    asm volatile("cp.async.cg.shared.global [%0], [%1], 16;" \
                 :: "r"(dst), "l"(src) : "memory")
#define CP_COMMIT() asm volatile("cp.async.commit_group;" ::: "memory")
#define CP_WAIT2()  asm volatile("cp.async.wait_group 2;" ::: "memory")

#define LDSM_X4(r0, r1, r2, r3, addr) \
    asm volatile("ldmatrix.sync.aligned.m8n8.x4.shared.b16 {%0,%1,%2,%3}, [%4];" \
                 : "=r"(r0), "=r"(r1), "=r"(r2), "=r"(r3) : "r"(addr))

#define MMA_BF16(d, a0, a1, a2, a3, b0, b1) \
    asm volatile("mma.sync.aligned.m16n8k16.row.col.f32.bf16.bf16.f32 " \
                 "{%0,%1,%2,%3}, {%4,%5,%6,%7}, {%8,%9}, {%0,%1,%2,%3};" \
                 : "+f"((d)[0]), "+f"((d)[1]), "+f"((d)[2]), "+f"((d)[3]) \
                 : "r"(a0), "r"(a1), "r"(a2), "r"(a3), "r"(b0), "r"(b1))

__device__ __forceinline__ void bsplit(float a, __nv_bfloat16& hi, __nv_bfloat16& lo) {
    hi = __float2bfloat16(a);
    lo = __float2bfloat16(a - __bfloat162float(hi));
}

// ---------------------------------------------------------------------------
// HMMA GEMM: C[128x128 tile] = tanh( A'[M,KP] @ B'[N,KP]^T + bias )
// 256 threads = 8 warps (2 M x 4 N), warp tile 64x32, BK=32, 4-stage cp.async.
// SMEM row = 32 bf16 (64 B) padded to 80 B -> conflict-free ldmatrix.
//   MODE 0: fp32 out to Cf (ldc = OUT_DIM)
//   MODE 1: bf16 triple [hi|hi|lo] to Cb (row stride KP2, segment H_DIM)
// ---------------------------------------------------------------------------
#define BK        32
#define ROWB      80                       // padded row stride (bytes)
#define TILE_B    (128 * ROWB)             // 10240 per operand per stage
#define STAGES    4
#define SMEM_SZ   (2 * STAGES * TILE_B)    // 81920

template <int MODE>
__global__ void __launch_bounds__(256, 1)
hmma_gemm(const __nv_bfloat16* __restrict__ A,
          const __nv_bfloat16* __restrict__ Bw,
          const float* __restrict__ bias,
          float* __restrict__ Cf,
          __nv_bfloat16* __restrict__ Cb,
          int KP)
{
    extern __shared__ char smem[];
    const uint32_t sb = smem_u32(smem);
    const int tid  = threadIdx.x;
    const int wid  = tid >> 5;
    const int lane = tid & 31;
    const int warp_m = wid & 1;            // 0..1  (64 rows each)
    const int warp_n = wid >> 1;           // 0..3  (32 cols each)
    const int row0 = blockIdx.y * 128;
    const int col0 = blockIdx.x * 128;

    const __nv_bfloat16* Ag = A  + (size_t)row0 * KP;
    const __nv_bfloat16* Bg = Bw + (size_t)col0 * KP;
    const int nc = KP / BK;

    // per-thread loader coords: 512 16B-chunks per operand per stage
    const int l_row0 = tid >> 2;           // chunk idx = tid, tid+256
    const int l_chk0 = (tid & 3) * 16;     // byte offset within 64B row
    const int l_row1 = (tid + 256) >> 2;
    const int l_chk1 = ((tid + 256) & 3) * 16;

    auto load_stage = [&](int buf, int c) {
        const int k0 = c * BK;
        uint32_t a_s = sb + buf * TILE_B;
        uint32_t b_s = sb + STAGES * TILE_B + buf * TILE_B;
        const char* ap = (const char*)(Ag + k0);
        const char* bp = (const char*)(Bg + k0);
        CP_ASYNC16(a_s + l_row0 * ROWB + l_chk0, ap + (size_t)l_row0 * KP * 2 + l_chk0);
        CP_ASYNC16(a_s + l_row1 * ROWB + l_chk1, ap + (size_t)l_row1 * KP * 2 + l_chk1);
        CP_ASYNC16(b_s + l_row0 * ROWB + l_chk0, bp + (size_t)l_row0 * KP * 2 + l_chk0);
        CP_ASYNC16(b_s + l_row1 * ROWB + l_chk1, bp + (size_t)l_row1 * KP * 2 + l_chk1);
    };

    float acc[4][4][4];
#pragma unroll
    for (int i = 0; i < 4; i++)
#pragma unroll
        for (int j = 0; j < 4; j++)
#pragma unroll
            for (int e = 0; e < 4; e++) acc[i][j][e] = 0.0f;

    // prologue: stages 0..2
#pragma unroll
    for (int s = 0; s < STAGES - 1; ++s) {
        if (s < nc) load_stage(s, s);
        CP_COMMIT();
    }

    // ldmatrix per-lane address components (within a stage buffer)
    const uint32_t a_lm_off =
        (uint32_t)((warp_m * 64 + (lane & 15)) * ROWB + (lane >> 4) * 16);
    const uint32_t b_lm_off =
        (uint32_t)((warp_n * 32 + (lane & 7) + ((lane >> 4) << 3)) * ROWB
                   + ((lane >> 3) & 1) * 16);

    for (int c = 0; c < nc; ++c) {
        CP_WAIT2();
        __syncthreads();
        if (c + STAGES - 1 < nc) load_stage((c + STAGES - 1) & (STAGES - 1), c + STAGES - 1);
        CP_COMMIT();

        const int buf = c & (STAGES - 1);
        const uint32_t a_s = sb + buf * TILE_B;
        const uint32_t b_s = sb + STAGES * TILE_B + buf * TILE_B;

#pragma unroll
        for (int kk = 0; kk < 2; ++kk) {               // two k16 steps
            const uint32_t koff = (uint32_t)(kk * 32); // 16 bf16 = 32 B
            uint32_t a[4][4], b[4][2];
#pragma unroll
            for (int mt = 0; mt < 4; ++mt) {
                uint32_t addr = a_s + a_lm_off + (uint32_t)(mt * 16 * ROWB) + koff;
                LDSM_X4(a[mt][0], a[mt][1], a[mt][2], a[mt][3], addr);
            }
#pragma unroll
            for (int np = 0; np < 2; ++np) {
                uint32_t addr = b_s + b_lm_off + (uint32_t)(np * 16 * ROWB) + koff;
                LDSM_X4(b[np * 2][0], b[np * 2][1], b[np * 2 + 1][0], b[np * 2 + 1][1], addr);
            }
#pragma unroll
            for (int mt = 0; mt < 4; ++mt)
#pragma unroll
                for (int nt = 0; nt < 4; ++nt)
                    MMA_BF16(acc[mt][nt], a[mt][0], a[mt][1], a[mt][2], a[mt][3],
                             b[nt][0], b[nt][1]);
        }
    }

    // epilogue: thread t holds (r_lo, c),(r_lo, c+1),(r_hi, c),(r_hi, c+1)
#pragma unroll
    for (int mt = 0; mt < 4; ++mt) {
        const int r_lo = row0 + warp_m * 64 + mt * 16 + (lane >> 2);
#pragma unroll
        for (int nt = 0; nt < 4; ++nt) {
            const int gc = col0 + warp_n * 32 + nt * 8 + (lane & 3) * 2;
            const float b0 = bias[gc], b1 = bias[gc + 1];
#pragma unroll
            for (int h = 0; h < 2; ++h) {
                const int r = r_lo + h * 8;
                float t0 = tanhf(acc[mt][nt][h * 2 + 0] + b0);
                float t1 = tanhf(acc[mt][nt][h * 2 + 1] + b1);
                if (MODE == 0) {
                    float2 v = make_float2(t0, t1);
                    *(float2*)(Cf + (size_t)r * OUT_DIM + gc) = v;
                } else {
                    __nv_bfloat16 h0, l0, h1, l1;
                    bsplit(t0, h0, l0);
                    bsplit(t1, h1, l1);
                    __nv_bfloat162 hh = __halves2bfloat162(h0, h1);
                    __nv_bfloat162 ll = __halves2bfloat162(l0, l1);
                    __nv_bfloat16* outp = Cb + (size_t)r * KP2;
                    *(__nv_bfloat162*)(outp + gc)              = hh;
                    *(__nv_bfloat162*)(outp + H_DIM + gc)      = hh;
                    *(__nv_bfloat162*)(outp + 2 * H_DIM + gc)  = ll;
                }
            }
        }
    }
}

// ---------------------------------------------------------------------------
// Prep kernels
// ---------------------------------------------------------------------------
__global__ void prep_v(const float* __restrict__ v_in, __nv_bfloat16* __restrict__ A1)
{
    int i = blockIdx.x * blockDim.x + threadIdx.x;
    if (i >= B_DIM * N_DIM) return;
    int m = i / N_DIM, k = i % N_DIM;
    float a = v_in[(size_t)m * (2 * N_DIM) + k] - 0.5f;
    __nv_bfloat16 hi, lo;
    bsplit(a, hi, lo);
    size_t base = (size_t)m * KP1;
    A1[base + k]             = hi;
    A1[base + N_DIM + k]     = hi;
    A1[base + 2 * N_DIM + k] = lo;
}

// W[Kk, Nn] row-major -> B'[Nn, 3*Kk]: [hi | lo | hi]
__global__ void prep_w(const float* __restrict__ W, __nv_bfloat16* __restrict__ Bp,
                       int Kk, int Nn)
{
    int idx = blockIdx.x * blockDim.x + threadIdx.x;
    if (idx >= Kk * Nn) return;
    int k = idx / Nn, n = idx % Nn;
    __nv_bfloat16 hi, lo;
    bsplit(W[idx], hi, lo);
    size_t base = (size_t)n * (3 * Kk);
    Bp[base + k]          = hi;
    Bp[base + Kk + k]     = lo;
    Bp[base + 2 * Kk + k] = hi;
}

// ---------------------------------------------------------------------------
// Spline transform + log-density (unchanged; ~memory-bound at 97us)
// ---------------------------------------------------------------------------
__global__ void __launch_bounds__(512)
spline_kernel(const float* __restrict__ v_in,
              const float* __restrict__ logd,
              const float* __restrict__ net,
              float* __restrict__ out)
{
    __shared__ float red[16];
    const int b = blockIdx.x;
    const int n = threadIdx.x;

    const float* p = net + (size_t)b * OUT_DIM + (size_t)n * (2 * K_SPL + 1);

    float h[K_SPL + 1];
#pragma unroll
    for (int i = 0; i <= K_SPL; i++) h[i] = p[i];
    float w[K_SPL];
#pragma unroll
    for (int j = 0; j < K_SPL; j++) w[j] = p[K_SPL + 1 + j];

    float m = w[0];
#pragma unroll
    for (int j = 1; j < K_SPL; j++) m = fmaxf(m, w[j]);
    float s = 0.0f;
#pragma unroll
    for (int j = 0; j < K_SPL; j++) { w[j] = expf(w[j] - m); s += w[j]; }
    const float inv_s = 1.0f / s;
#pragma unroll
    for (int j = 0; j < K_SPL; j++) w[j] *= inv_s;

    float eh[K_SPL + 1];
#pragma unroll
    for (int i = 0; i <= K_SPL; i++) eh[i] = expf(h[i]);
    float denom = 0.0f;
#pragma unroll
    for (int j = 0; j < K_SPL; j++) denom += 0.5f * w[j] * (eh[j] + eh[j + 1]);
    const float inv_d = 1.0f / denom;
    float hn[K_SPL + 1];
#pragma unroll
    for (int i = 0; i <= K_SPL; i++) hn[i] = eh[i] * inv_d;

    const float vp = v_in[(size_t)b * (2 * N_DIM) + n];
    const float va = v_in[(size_t)b * (2 * N_DIM) + N_DIM + n];

    int cnt = (0.0f < va) ? 1 : 0;
    {
        float cum = 0.0f;
#pragma unroll
        for (int j = 0; j < K_SPL; j++) {
            cum += w[j];
            cnt += (cum < va) ? 1 : 0;
        }
    }
    int k = cnt - 1;
    k = k < 0 ? 0 : (k > K_SPL - 1 ? K_SPL - 1 : k);

    float xlo = 0.0f, ylo = 0.0f;
    float wseg = w[0], hlo = hn[0], hhi = hn[1];
    {
        float cum = 0.0f, ysum = 0.0f;
#pragma unroll
        for (int j = 0; j < K_SPL; j++) {
            if (j == k) { xlo = cum; ylo = ysum; wseg = w[j]; hlo = hn[j]; hhi = hn[j + 1]; }
            cum  += w[j];
            ysum += 0.5f * w[j] * (hn[j] + hn[j + 1]);
        }
    }

    const float alpha = (va - xlo) / wseg;
    const float vo = ylo + alpha * hlo * wseg
                   + 0.5f * alpha * alpha * (hhi - hlo) * wseg;

    out[(size_t)b * (2 * N_DIM) + n]         = vp;
    out[(size_t)b * (2 * N_DIM) + N_DIM + n] = vo;

    float lg = logf(hlo + alpha * (hhi - hlo));
#pragma unroll
    for (int off = 16; off > 0; off >>= 1)
        lg += __shfl_down_sync(0xffffffffu, lg, off);
    if ((n & 31) == 0) red[n >> 5] = lg;
    __syncthreads();
    if (n < 16) {
        float v = red[n];
#pragma unroll
        for (int off = 8; off > 0; off >>= 1)
            v += __shfl_down_sync(0x0000ffffu, v, off);
        if (n == 0)
            out[(size_t)B_DIM * (2 * N_DIM) + b] = logd[b] - v;
    }
}

// ---------------------------------------------------------------------------
// Launch
// ---------------------------------------------------------------------------
extern "C" void kernel_launch(void* const* d_in, const int* in_sizes, int n_in,
                              void* d_out, int out_size)
{
    const float* v_in = (const float*)d_in[0];
    const float* logd = (const float*)d_in[1];
    const float* W1   = (const float*)d_in[2];
    const float* b1   = (const float*)d_in[3];
    const float* W2   = (const float*)d_in[4];
    const float* b2   = (const float*)d_in[5];
    const float* W3   = (const float*)d_in[6];
    const float* b3   = (const float*)d_in[7];
    float* out = (float*)d_out;

    __nv_bfloat16 *A1, *A2, *A3, *B1v, *B2v, *B3v;
    float* net;
    cudaGetSymbolAddress((void**)&A1, g_A1);
    cudaGetSymbolAddress((void**)&A2, g_A2);
    cudaGetSymbolAddress((void**)&A3, g_A3);
    cudaGetSymbolAddress((void**)&B1v, g_B1);
    cudaGetSymbolAddress((void**)&B2v, g_B2);
    cudaGetSymbolAddress((void**)&B3v, g_B3);
    cudaGetSymbolAddress((void**)&net, g_net);

    cudaFuncSetAttribute((const void*)hmma_gemm<0>,
                         cudaFuncAttributeMaxDynamicSharedMemorySize, SMEM_SZ);
    cudaFuncSetAttribute((const void*)hmma_gemm<1>,
                         cudaFuncAttributeMaxDynamicSharedMemorySize, SMEM_SZ);

    // operand splitting / weight transpose
    prep_v<<<(B_DIM * N_DIM + 255) / 256, 256>>>(v_in, A1);
    prep_w<<<(N_DIM * H_DIM + 255) / 256, 256>>>(W1, B1v, N_DIM, H_DIM);
    prep_w<<<(H_DIM * H_DIM + 255) / 256, 256>>>(W2, B2v, H_DIM, H_DIM);
    prep_w<<<(H_DIM * OUT_DIM + 255) / 256, 256>>>(W3, B3v, H_DIM, OUT_DIM);

    // G1: x1 (bf16 triple) = tanh((v_p - 0.5) @ W1 + b1)
    hmma_gemm<1><<<dim3(H_DIM / 128, B_DIM / 128), 256, SMEM_SZ>>>(
        A1, B1v, b1, nullptr, A2, KP1);
    // G2: x2 (bf16 triple) = tanh(x1 @ W2 + b2)
    hmma_gemm<1><<<dim3(H_DIM / 128, B_DIM / 128), 256, SMEM_SZ>>>(
        A2, B2v, b2, nullptr, A3, KP2);
    // G3: net (fp32) = tanh(x2 @ W3 + b3)
    hmma_gemm<0><<<dim3(OUT_DIM / 128, B_DIM / 128), 256, SMEM_SZ>>>(
        A3, B3v, b3, net, nullptr, KP2);

    // spline + log-density
    spline_kernel<<<B_DIM, 512>>>(v_in, logd, net, out);
}

// round 17
// speedup vs baseline: 1.5654x; 1.0008x over previous
#include <cuda_runtime.h>
#include <cuda_bf16.h>
#include <math.h>
#include <stdint.h>

// ---------------------------------------------------------------------------
// Problem dims (fixed)
// ---------------------------------------------------------------------------
#define B_DIM   8192
#define N_DIM   512
#define K_SPL   8
#define H_DIM   1024
#define OUT_DIM (N_DIM * (2 * K_SPL + 1))   // 8704
#define KP1     (3 * N_DIM)                 // 1536
#define KP2     (3 * H_DIM)                 // 3072

// ---------------------------------------------------------------------------
// Scratch (__device__ globals).
// A' = [Ah | Ah | Al],  B' = [Bh | Bl | Bh] along K  =>
//   A'@B'^T = Ah·Bh + Ah·Bl + Al·Bh  (drops Al·Bl ~ 2^-16)
// ---------------------------------------------------------------------------
__device__ __align__(128) __nv_bfloat16 g_A1[(size_t)B_DIM * KP1];
__device__ __align__(128) __nv_bfloat16 g_A2[(size_t)B_DIM * KP2];
__device__ __align__(128) __nv_bfloat16 g_A3[(size_t)B_DIM * KP2];
__device__ __align__(128) __nv_bfloat16 g_B1[(size_t)H_DIM * KP1];
__device__ __align__(128) __nv_bfloat16 g_B2[(size_t)H_DIM * KP2];
__device__ __align__(128) __nv_bfloat16 g_B3[(size_t)OUT_DIM * KP2];
__device__ __align__(128) float         g_net[(size_t)B_DIM * OUT_DIM];

// ---------------------------------------------------------------------------
// Helpers (all baseline sm_80+ PTX — compiles under compute_103)
// ---------------------------------------------------------------------------
__device__ __forceinline__ uint32_t smem_u32(const void* p) {
    uint32_t a;
    asm("{ .reg .u64 t; cvta.to.shared.u64 t, %1; cvt.u32.u64 %0, t; }"
        : "=r"(a) : "l"(p));
    return a;
}

#define CP_ASYNC16(dst, src) \
    asm volatile("cp.async.cg.shared.global [%0], [%1], 16;" \
                 :: "r"(dst), "l"(src) : "memory")
#define CP_COMMIT() asm volatile("cp.async.commit_group;" ::: "memory")
#define CP_WAIT2()  asm volatile("cp.async.wait_group 2;" ::: "memory")

#define LDSM_X4(r0, r1, r2, r3, addr) \
    asm volatile("ldmatrix.sync.aligned.m8n8.x4.shared.b16 {%0,%1,%2,%3}, [%4];" \
                 : "=r"(r0), "=r"(r1), "=r"(r2), "=r"(r3) : "r"(addr))

#define MMA_BF16(d, a0, a1, a2, a3, b0, b1) \
    asm volatile("mma.sync.aligned.m16n8k16.row.col.f32.bf16.bf16.f32 " \
                 "{%0,%1,%2,%3}, {%4,%5,%6,%7}, {%8,%9}, {%0,%1,%2,%3};" \
                 : "+f"((d)[0]), "+f"((d)[1]), "+f"((d)[2]), "+f"((d)[3]) \
                 : "r"(a0), "r"(a1), "r"(a2), "r"(a3), "r"(b0), "r"(b1))

__device__ __forceinline__ void bsplit(float a, __nv_bfloat16& hi, __nv_bfloat16& lo) {
    hi = __float2bfloat16(a);
    lo = __float2bfloat16(a - __bfloat162float(hi));
}

// ---------------------------------------------------------------------------
// HMMA GEMM: C[128x128 tile] = tanh( A'[M,KP] @ B'[N,KP]^T + bias )
// 256 threads = 8 warps (2 M x 4 N), warp tile 64x32, BK=32, 4-stage cp.async.
// SMEM row = 32 bf16 (64 B) padded to 80 B -> conflict-free ldmatrix.
//   MODE 0: fp32 out to Cf (ldc = OUT_DIM)
//   MODE 1: bf16 triple [hi|hi|lo] to Cb (row stride KP2, segment H_DIM)
// ---------------------------------------------------------------------------
#define BK        32
#define ROWB      80                       // padded row stride (bytes)
#define TILE_B    (128 * ROWB)             // 10240 per operand per stage
#define STAGES    4
#define SMEM_SZ   (2 * STAGES * TILE_B)    // 81920

template <int MODE>
__global__ void __launch_bounds__(256, 1)
hmma_gemm(const __nv_bfloat16* __restrict__ A,
          const __nv_bfloat16* __restrict__ Bw,
          const float* __restrict__ bias,
          float* __restrict__ Cf,
          __nv_bfloat16* __restrict__ Cb,
          int KP)
{
    extern __shared__ char smem[];
    const uint32_t sb = smem_u32(smem);
    const int tid  = threadIdx.x;
    const int wid  = tid >> 5;
    const int lane = tid & 31;
    const int warp_m = wid & 1;            // 0..1  (64 rows each)
    const int warp_n = wid >> 1;           // 0..3  (32 cols each)
    const int row0 = blockIdx.y * 128;
    const int col0 = blockIdx.x * 128;

    const __nv_bfloat16* Ag = A  + (size_t)row0 * KP;
    const __nv_bfloat16* Bg = Bw + (size_t)col0 * KP;
    const int nc = KP / BK;

    // per-thread loader coords: 512 16B-chunks per operand per stage
    const int l_row0 = tid >> 2;           // chunk idx = tid, tid+256
    const int l_chk0 = (tid & 3) * 16;     // byte offset within 64B row
    const int l_row1 = (tid + 256) >> 2;
    const int l_chk1 = ((tid + 256) & 3) * 16;

    auto load_stage = [&](int buf, int c) {
        const int k0 = c * BK;
        uint32_t a_s = sb + buf * TILE_B;
        uint32_t b_s = sb + STAGES * TILE_B + buf * TILE_B;
        const char* ap = (const char*)(Ag + k0);
        const char* bp = (const char*)(Bg + k0);
        CP_ASYNC16(a_s + l_row0 * ROWB + l_chk0, ap + (size_t)l_row0 * KP * 2 + l_chk0);
        CP_ASYNC16(a_s + l_row1 * ROWB + l_chk1, ap + (size_t)l_row1 * KP * 2 + l_chk1);
        CP_ASYNC16(b_s + l_row0 * ROWB + l_chk0, bp + (size_t)l_row0 * KP * 2 + l_chk0);
        CP_ASYNC16(b_s + l_row1 * ROWB + l_chk1, bp + (size_t)l_row1 * KP * 2 + l_chk1);
    };

    float acc[4][4][4];
#pragma unroll
    for (int i = 0; i < 4; i++)
#pragma unroll
        for (int j = 0; j < 4; j++)
#pragma unroll
            for (int e = 0; e < 4; e++) acc[i][j][e] = 0.0f;

    // prologue: stages 0..2
#pragma unroll
    for (int s = 0; s < STAGES - 1; ++s) {
        if (s < nc) load_stage(s, s);
        CP_COMMIT();
    }

    // ldmatrix per-lane address components (within a stage buffer)
    const uint32_t a_lm_off =
        (uint32_t)((warp_m * 64 + (lane & 15)) * ROWB + (lane >> 4) * 16);
    const uint32_t b_lm_off =
        (uint32_t)((warp_n * 32 + (lane & 7) + ((lane >> 4) << 3)) * ROWB
                   + ((lane >> 3) & 1) * 16);

    for (int c = 0; c < nc; ++c) {
        CP_WAIT2();
        __syncthreads();
        if (c + STAGES - 1 < nc) load_stage((c + STAGES - 1) & (STAGES - 1), c + STAGES - 1);
        CP_COMMIT();

        const int buf = c & (STAGES - 1);
        const uint32_t a_s = sb + buf * TILE_B;
        const uint32_t b_s = sb + STAGES * TILE_B + buf * TILE_B;

#pragma unroll
        for (int kk = 0; kk < 2; ++kk) {               // two k16 steps
            const uint32_t koff = (uint32_t)(kk * 32); // 16 bf16 = 32 B
            uint32_t a[4][4], b[4][2];
#pragma unroll
            for (int mt = 0; mt < 4; ++mt) {
                uint32_t addr = a_s + a_lm_off + (uint32_t)(mt * 16 * ROWB) + koff;
                LDSM_X4(a[mt][0], a[mt][1], a[mt][2], a[mt][3], addr);
            }
#pragma unroll
            for (int np = 0; np < 2; ++np) {
                uint32_t addr = b_s + b_lm_off + (uint32_t)(np * 16 * ROWB) + koff;
                LDSM_X4(b[np * 2][0], b[np * 2][1], b[np * 2 + 1][0], b[np * 2 + 1][1], addr);
            }
#pragma unroll
            for (int mt = 0; mt < 4; ++mt)
#pragma unroll
                for (int nt = 0; nt < 4; ++nt)
                    MMA_BF16(acc[mt][nt], a[mt][0], a[mt][1], a[mt][2], a[mt][3],
                             b[nt][0], b[nt][1]);
        }
    }

    // epilogue: thread t holds (r_lo, c),(r_lo, c+1),(r_hi, c),(r_hi, c+1)
#pragma unroll
    for (int mt = 0; mt < 4; ++mt) {
        const int r_lo = row0 + warp_m * 64 + mt * 16 + (lane >> 2);
#pragma unroll
        for (int nt = 0; nt < 4; ++nt) {
            const int gc = col0 + warp_n * 32 + nt * 8 + (lane & 3) * 2;
            const float b0 = bias[gc], b1 = bias[gc + 1];
#pragma unroll
            for (int h = 0; h < 2; ++h) {
                const int r = r_lo + h * 8;
                float t0 = tanhf(acc[mt][nt][h * 2 + 0] + b0);
                float t1 = tanhf(acc[mt][nt][h * 2 + 1] + b1);
                if (MODE == 0) {
                    float2 v = make_float2(t0, t1);
                    *(float2*)(Cf + (size_t)r * OUT_DIM + gc) = v;
                } else {
                    __nv_bfloat16 h0, l0, h1, l1;
                    bsplit(t0, h0, l0);
                    bsplit(t1, h1, l1);
                    __nv_bfloat162 hh = __halves2bfloat162(h0, h1);
                    __nv_bfloat162 ll = __halves2bfloat162(l0, l1);
                    __nv_bfloat16* outp = Cb + (size_t)r * KP2;
                    *(__nv_bfloat162*)(outp + gc)              = hh;
                    *(__nv_bfloat162*)(outp + H_DIM + gc)      = hh;
                    *(__nv_bfloat162*)(outp + 2 * H_DIM + gc)  = ll;
                }
            }
        }
    }
}

// ---------------------------------------------------------------------------
// Prep kernels
// ---------------------------------------------------------------------------
__global__ void prep_v(const float* __restrict__ v_in, __nv_bfloat16* __restrict__ A1)
{
    int i = blockIdx.x * blockDim.x + threadIdx.x;
    if (i >= B_DIM * N_DIM) return;
    int m = i / N_DIM, k = i % N_DIM;
    float a = v_in[(size_t)m * (2 * N_DIM) + k] - 0.5f;
    __nv_bfloat16 hi, lo;
    bsplit(a, hi, lo);
    size_t base = (size_t)m * KP1;
    A1[base + k]             = hi;
    A1[base + N_DIM + k]     = hi;
    A1[base + 2 * N_DIM + k] = lo;
}

// W[Kk, Nn] row-major -> B'[Nn, 3*Kk]: [hi | lo | hi]
__global__ void prep_w(const float* __restrict__ W, __nv_bfloat16* __restrict__ Bp,
                       int Kk, int Nn)
{
    int idx = blockIdx.x * blockDim.x + threadIdx.x;
    if (idx >= Kk * Nn) return;
    int k = idx / Nn, n = idx % Nn;
    __nv_bfloat16 hi, lo;
    bsplit(W[idx], hi, lo);
    size_t base = (size_t)n * (3 * Kk);
    Bp[base + k]          = hi;
    Bp[base + Kk + k]     = lo;
    Bp[base + 2 * Kk + k] = hi;
}

// ---------------------------------------------------------------------------
// Spline transform + log-density (unchanged; ~memory-bound at 97us)
// ---------------------------------------------------------------------------
__global__ void __launch_bounds__(512)
spline_kernel(const float* __restrict__ v_in,
              const float* __restrict__ logd,
              const float* __restrict__ net,
              float* __restrict__ out)
{
    __shared__ float red[16];
    const int b = blockIdx.x;
    const int n = threadIdx.x;

    const float* p = net + (size_t)b * OUT_DIM + (size_t)n * (2 * K_SPL + 1);

    float h[K_SPL + 1];
#pragma unroll
    for (int i = 0; i <= K_SPL; i++) h[i] = p[i];
    float w[K_SPL];
#pragma unroll
    for (int j = 0; j < K_SPL; j++) w[j] = p[K_SPL + 1 + j];

    float m = w[0];
#pragma unroll
    for (int j = 1; j < K_SPL; j++) m = fmaxf(m, w[j]);
    float s = 0.0f;
#pragma unroll
    for (int j = 0; j < K_SPL; j++) { w[j] = expf(w[j] - m); s += w[j]; }
    const float inv_s = 1.0f / s;
#pragma unroll
    for (int j = 0; j < K_SPL; j++) w[j] *= inv_s;

    float eh[K_SPL + 1];
#pragma unroll
    for (int i = 0; i <= K_SPL; i++) eh[i] = expf(h[i]);
    float denom = 0.0f;
#pragma unroll
    for (int j = 0; j < K_SPL; j++) denom += 0.5f * w[j] * (eh[j] + eh[j + 1]);
    const float inv_d = 1.0f / denom;
    float hn[K_SPL + 1];
#pragma unroll
    for (int i = 0; i <= K_SPL; i++) hn[i] = eh[i] * inv_d;

    const float vp = v_in[(size_t)b * (2 * N_DIM) + n];
    const float va = v_in[(size_t)b * (2 * N_DIM) + N_DIM + n];

    int cnt = (0.0f < va) ? 1 : 0;
    {
        float cum = 0.0f;
#pragma unroll
        for (int j = 0; j < K_SPL; j++) {
            cum += w[j];
            cnt += (cum < va) ? 1 : 0;
        }
    }
    int k = cnt - 1;
    k = k < 0 ? 0 : (k > K_SPL - 1 ? K_SPL - 1 : k);

    float xlo = 0.0f, ylo = 0.0f;
    float wseg = w[0], hlo = hn[0], hhi = hn[1];
    {
        float cum = 0.0f, ysum = 0.0f;
#pragma unroll
        for (int j = 0; j < K_SPL; j++) {
            if (j == k) { xlo = cum; ylo = ysum; wseg = w[j]; hlo = hn[j]; hhi = hn[j + 1]; }
            cum  += w[j];
            ysum += 0.5f * w[j] * (hn[j] + hn[j + 1]);
        }
    }

    const float alpha = (va - xlo) / wseg;
    const float vo = ylo + alpha * hlo * wseg
                   + 0.5f * alpha * alpha * (hhi - hlo) * wseg;

    out[(size_t)b * (2 * N_DIM) + n]         = vp;
    out[(size_t)b * (2 * N_DIM) + N_DIM + n] = vo;

    float lg = logf(hlo + alpha * (hhi - hlo));
#pragma unroll
    for (int off = 16; off > 0; off >>= 1)
        lg += __shfl_down_sync(0xffffffffu, lg, off);
    if ((n & 31) == 0) red[n >> 5] = lg;
    __syncthreads();
    if (n < 16) {
        float v = red[n];
#pragma unroll
        for (int off = 8; off > 0; off >>= 1)
            v += __shfl_down_sync(0x0000ffffu, v, off);
        if (n == 0)
            out[(size_t)B_DIM * (2 * N_DIM) + b] = logd[b] - v;
    }
}

// ---------------------------------------------------------------------------
// Launch
// ---------------------------------------------------------------------------
extern "C" void kernel_launch(void* const* d_in, const int* in_sizes, int n_in,
                              void* d_out, int out_size)
{
    const float* v_in = (const float*)d_in[0];
    const float* logd = (const float*)d_in[1];
    const float* W1   = (const float*)d_in[2];
    const float* b1   = (const float*)d_in[3];
    const float* W2   = (const float*)d_in[4];
    const float* b2   = (const float*)d_in[5];
    const float* W3   = (const float*)d_in[6];
    const float* b3   = (const float*)d_in[7];
    float* out = (float*)d_out;

    __nv_bfloat16 *A1, *A2, *A3, *B1v, *B2v, *B3v;
    float* net;
    cudaGetSymbolAddress((void**)&A1, g_A1);
    cudaGetSymbolAddress((void**)&A2, g_A2);
    cudaGetSymbolAddress((void**)&A3, g_A3);
    cudaGetSymbolAddress((void**)&B1v, g_B1);
    cudaGetSymbolAddress((void**)&B2v, g_B2);
    cudaGetSymbolAddress((void**)&B3v, g_B3);
    cudaGetSymbolAddress((void**)&net, g_net);

    cudaFuncSetAttribute((const void*)hmma_gemm<0>,
                         cudaFuncAttributeMaxDynamicSharedMemorySize, SMEM_SZ);
    cudaFuncSetAttribute((const void*)hmma_gemm<1>,
                         cudaFuncAttributeMaxDynamicSharedMemorySize, SMEM_SZ);

    // operand splitting / weight transpose
    prep_v<<<(B_DIM * N_DIM + 255) / 256, 256>>>(v_in, A1);
    prep_w<<<(N_DIM * H_DIM + 255) / 256, 256>>>(W1, B1v, N_DIM, H_DIM);
    prep_w<<<(H_DIM * H_DIM + 255) / 256, 256>>>(W2, B2v, H_DIM, H_DIM);
    prep_w<<<(H_DIM * OUT_DIM + 255) / 256, 256>>>(W3, B3v, H_DIM, OUT_DIM);

    // G1: x1 (bf16 triple) = tanh((v_p - 0.5) @ W1 + b1)
    hmma_gemm<1><<<dim3(H_DIM / 128, B_DIM / 128), 256, SMEM_SZ>>>(
        A1, B1v, b1, nullptr, A2, KP1);
    // G2: x2 (bf16 triple) = tanh(x1 @ W2 + b2)
    hmma_gemm<1><<<dim3(H_DIM / 128, B_DIM / 128), 256, SMEM_SZ>>>(
        A2, B2v, b2, nullptr, A3, KP2);
    // G3: net (fp32) = tanh(x2 @ W3 + b3)
    hmma_gemm<0><<<dim3(OUT_DIM / 128, B_DIM / 128), 256, SMEM_SZ>>>(
        A3, B3v, b3, net, nullptr, KP2);

    // spline + log-density
    spline_kernel<<<B_DIM, 512>>>(v_in, logd, net, out);
}